// round 1
// baseline (speedup 1.0000x reference)
#include <cuda_runtime.h>

// SparseDownSample: 2x2 max-pool keyed on depth (first-max tie-break),
// gather winning position from depth (1ch) and geo (16ch).
// depth: [B,1,H,W] f32, geo: [B,C,H,W] f32
// out  : depth_fold [B,1,H/2,W/2] followed by geo_fold [B,C,H/2,W/2]

constexpr int B  = 8;
constexpr int C  = 16;
constexpr int H  = 352;
constexpr int W  = 1216;
constexpr int H2 = H / 2;    // 176
constexpr int W2 = W / 2;    // 608
constexpr int WP = W2 / 2;   // 304 output-pixel PAIRS per row (one float4 of input per row)
constexpr int DEPTH_OUT_ELEMS = B * H2 * W2;  // 856064

__global__ __launch_bounds__(256)
void sds_kernel(const float* __restrict__ depth,
                const float* __restrict__ geo,
                float* __restrict__ out)
{
    const int t = blockIdx.x * blockDim.x + threadIdx.x;
    const int total = B * H2 * WP;   // 428032
    if (t >= total) return;

    const int xp   = t % WP;         // which float4 within the row
    const int rest = t / WP;
    const int y    = rest % H2;
    const int b    = rest / H2;

    // ---- depth: two rows, one float4 each (covers 2 output pixels) ----
    const float4* dr0 = reinterpret_cast<const float4*>(
        depth + (size_t)(b * H + 2 * y) * W) + xp;
    const float4* dr1 = reinterpret_cast<const float4*>(
        depth + (size_t)(b * H + 2 * y + 1) * W) + xp;
    const float4 d0 = __ldg(dr0);
    const float4 d1 = __ldg(dr1);

    // argmax, first-max wins (strict > keeps lowest index), order:
    // 0=(r0,c0) 1=(r0,c1) 2=(r1,c0) 3=(r1,c1)  -- matches unfold kh,kw ordering
    int   i0 = 0; float v0 = d0.x;
    if (d0.y > v0) { v0 = d0.y; i0 = 1; }
    if (d1.x > v0) { v0 = d1.x; i0 = 2; }
    if (d1.y > v0) { v0 = d1.y; i0 = 3; }

    int   i1 = 0; float v1 = d0.z;
    if (d0.w > v1) { v1 = d0.w; i1 = 1; }
    if (d1.z > v1) { v1 = d1.z; i1 = 2; }
    if (d1.w > v1) { v1 = d1.w; i1 = 3; }

    // depth_fold store (float2, 8B aligned: xp*2 is even)
    const size_t dpix = (size_t)(b * H2 + y) * W2 + (size_t)xp * 2;
    reinterpret_cast<float2*>(out)[dpix / 2] = make_float2(v0, v1);

    // ---- geo: 16 channels, same 2x2 window, select by i0/i1 ----
    float* gout = out + DEPTH_OUT_ELEMS;
    const float* gbase = geo + (size_t)b * C * H * W;

    #pragma unroll
    for (int c = 0; c < C; ++c) {
        const float4* g0p = reinterpret_cast<const float4*>(
            gbase + (size_t)(c * H + 2 * y) * W) + xp;
        const float4* g1p = reinterpret_cast<const float4*>(
            gbase + (size_t)(c * H + 2 * y + 1) * W) + xp;
        const float4 g0 = __ldg(g0p);
        const float4 g1 = __ldg(g1p);

        const float s0 = (i0 == 0) ? g0.x : (i0 == 1) ? g0.y : (i0 == 2) ? g1.x : g1.y;
        const float s1 = (i1 == 0) ? g0.z : (i1 == 1) ? g0.w : (i1 == 2) ? g1.z : g1.w;

        const size_t o = ((size_t)(b * C + c) * H2 + y) * W2 + (size_t)xp * 2;
        reinterpret_cast<float2*>(gout)[o / 2] = make_float2(s0, s1);
    }
}

extern "C" void kernel_launch(void* const* d_in, const int* in_sizes, int n_in,
                              void* d_out, int out_size)
{
    const float* depth = (const float*)d_in[0];
    const float* geo   = (const float*)d_in[1];
    float* out = (float*)d_out;

    const int total   = B * H2 * WP;          // 428032 threads
    const int threads = 256;
    const int blocks  = (total + threads - 1) / threads;
    sds_kernel<<<blocks, threads>>>(depth, geo, out);
}

// round 2
// speedup vs baseline: 1.0695x; 1.0695x over previous
#include <cuda_runtime.h>

// SparseDownSample: 2x2 max-pool keyed on depth (first-max tie-break),
// gather winning position from depth (1ch) and geo (16ch).
// depth: [B,1,H,W] f32, geo: [B,C,H,W] f32
// out  : depth_fold [B,1,H/2,W/2] followed by geo_fold [B,C,H/2,W/2]

constexpr int B  = 8;
constexpr int C  = 16;
constexpr int H  = 352;
constexpr int W  = 1216;
constexpr int H2 = H / 2;    // 176
constexpr int W2 = W / 2;    // 608
constexpr int WP = W2 / 2;   // 304 output-pixel PAIRS per row (one float4 of input per row)
constexpr int DEPTH_OUT_ELEMS = B * H2 * W2;  // 856064
constexpr int CB = 4;        // channels per load batch (8 float4 = 32 regs live)

__global__ __launch_bounds__(256)
void sds_kernel(const float* __restrict__ depth,
                const float* __restrict__ geo,
                float* __restrict__ out)
{
    const int t = blockIdx.x * blockDim.x + threadIdx.x;
    const int total = B * H2 * WP;   // 428032
    if (t >= total) return;

    const int xp   = t % WP;         // which float4 within the row
    const int rest = t / WP;
    const int y    = rest % H2;
    const int b    = rest / H2;

    // ---- depth: two rows, one float4 each (covers 2 output pixels) ----
    const float* drow = depth + (size_t)(b * H + 2 * y) * W;
    const float4 d0 = __ldg(reinterpret_cast<const float4*>(drow) + xp);
    const float4 d1 = __ldg(reinterpret_cast<const float4*>(drow + W) + xp);

    // argmax, first-max wins (strict > keeps lowest index), order:
    // 0=(r0,c0) 1=(r0,c1) 2=(r1,c0) 3=(r1,c1)  -- matches unfold kh,kw ordering
    int   i0 = 0; float v0 = d0.x;
    if (d0.y > v0) { v0 = d0.y; i0 = 1; }
    if (d1.x > v0) { v0 = d1.x; i0 = 2; }
    if (d1.y > v0) { v0 = d1.y; i0 = 3; }

    int   i1 = 0; float v1 = d0.z;
    if (d0.w > v1) { v1 = d0.w; i1 = 1; }
    if (d1.z > v1) { v1 = d1.z; i1 = 2; }
    if (d1.w > v1) { v1 = d1.w; i1 = 3; }

    // depth_fold store (float2, 8B aligned: xp*2 is even)
    const size_t dpix = (size_t)(b * H2 + y) * W2 + (size_t)xp * 2;
    reinterpret_cast<float2*>(out)[dpix / 2] = make_float2(v0, v1);

    // ---- geo: 16 channels in batches of CB; stage loads, then select ----
    float* gout = out + DEPTH_OUT_ELEMS;
    const float* grow = geo + ((size_t)b * C * H + 2 * y) * W;   // channel 0, row 2y
    const size_t obase = ((size_t)(b * C) * H2 + y) * W2 + (size_t)xp * 2;

    #pragma unroll
    for (int cb = 0; cb < C; cb += CB) {
        float4 g0[CB], g1[CB];
        // phase 1: issue all loads back-to-back (front-batched LDG.128, MLP=2*CB)
        #pragma unroll
        for (int j = 0; j < CB; ++j) {
            const float* r0 = grow + (size_t)(cb + j) * (H * W);
            g0[j] = __ldg(reinterpret_cast<const float4*>(r0) + xp);
            g1[j] = __ldg(reinterpret_cast<const float4*>(r0 + W) + xp);
        }
        // phase 2: select + store
        #pragma unroll
        for (int j = 0; j < CB; ++j) {
            const float s0 = (i0 == 0) ? g0[j].x : (i0 == 1) ? g0[j].y
                           : (i0 == 2) ? g1[j].x : g1[j].y;
            const float s1 = (i1 == 0) ? g0[j].z : (i1 == 1) ? g0[j].w
                           : (i1 == 2) ? g1[j].z : g1[j].w;
            const size_t o = obase + (size_t)(cb + j) * (H2 * W2);
            reinterpret_cast<float2*>(gout)[o / 2] = make_float2(s0, s1);
        }
    }
}

extern "C" void kernel_launch(void* const* d_in, const int* in_sizes, int n_in,
                              void* d_out, int out_size)
{
    const float* depth = (const float*)d_in[0];
    const float* geo   = (const float*)d_in[1];
    float* out = (float*)d_out;

    const int total   = B * H2 * WP;          // 428032 threads
    const int threads = 256;
    const int blocks  = (total + threads - 1) / threads;
    sds_kernel<<<blocks, threads>>>(depth, geo, out);
}

// round 3
// speedup vs baseline: 1.1905x; 1.1131x over previous
#include <cuda_runtime.h>

// SparseDownSample: 2x2 max-pool keyed on depth (first-max tie-break),
// gather winning position from depth (1ch) and geo (16ch).
// depth: [B,1,H,W] f32, geo: [B,C,H,W] f32
// out  : depth_fold [B,1,H/2,W/2] followed by geo_fold [B,C,H/2,W/2]

constexpr int B  = 8;
constexpr int C  = 16;
constexpr int H  = 352;
constexpr int W  = 1216;
constexpr int H2 = H / 2;    // 176
constexpr int W2 = W / 2;    // 608
constexpr int WP = W2 / 2;   // 304 output-pixel PAIRS per row (one float4 of input per row)
constexpr int DEPTH_OUT_ELEMS = B * H2 * W2;  // 856064
constexpr int CB = 8;        // channels per load batch (16 float4 = 64 regs live)

__global__ __launch_bounds__(256)
void sds_kernel(const float* __restrict__ depth,
                const float* __restrict__ geo,
                float* __restrict__ out)
{
    const int t = blockIdx.x * blockDim.x + threadIdx.x;
    const int total = B * H2 * WP;   // 428032
    if (t >= total) return;

    const int xp   = t % WP;         // which float4 within the row
    const int rest = t / WP;
    const int y    = rest % H2;
    const int b    = rest / H2;

    // ---- depth: two rows, one float4 each (covers 2 output pixels) ----
    const float* drow = depth + (size_t)(b * H + 2 * y) * W;
    const float4 d0 = __ldg(reinterpret_cast<const float4*>(drow) + xp);
    const float4 d1 = __ldg(reinterpret_cast<const float4*>(drow + W) + xp);

    // argmax, first-max wins (strict > keeps lowest index), order:
    // 0=(r0,c0) 1=(r0,c1) 2=(r1,c0) 3=(r1,c1)  -- matches unfold kh,kw ordering
    int   i0 = 0; float v0 = d0.x;
    if (d0.y > v0) { v0 = d0.y; i0 = 1; }
    if (d1.x > v0) { v0 = d1.x; i0 = 2; }
    if (d1.y > v0) { v0 = d1.y; i0 = 3; }

    int   i1 = 0; float v1 = d0.z;
    if (d0.w > v1) { v1 = d0.w; i1 = 1; }
    if (d1.z > v1) { v1 = d1.z; i1 = 2; }
    if (d1.w > v1) { v1 = d1.w; i1 = 3; }

    // depth_fold store (float2, 8B aligned: xp*2 is even)
    const size_t dpix = (size_t)(b * H2 + y) * W2 + (size_t)xp * 2;
    __stcs(reinterpret_cast<float2*>(out) + dpix / 2, make_float2(v0, v1));

    // ---- geo: 16 channels in batches of CB; stage loads, then select ----
    float* gout = out + DEPTH_OUT_ELEMS;
    const float* grow = geo + ((size_t)b * C * H + 2 * y) * W;   // channel 0, row 2y
    const size_t obase = ((size_t)(b * C) * H2 + y) * W2 + (size_t)xp * 2;

    #pragma unroll
    for (int cb = 0; cb < C; cb += CB) {
        float4 g0[CB], g1[CB];
        // phase 1: issue all loads back-to-back (front-batched LDG.128, MLP=2*CB)
        #pragma unroll
        for (int j = 0; j < CB; ++j) {
            const float* r0 = grow + (size_t)(cb + j) * (H * W);
            g0[j] = __ldcs(reinterpret_cast<const float4*>(r0) + xp);
            g1[j] = __ldcs(reinterpret_cast<const float4*>(r0 + W) + xp);
        }
        // phase 2: select + store
        #pragma unroll
        for (int j = 0; j < CB; ++j) {
            const float s0 = (i0 == 0) ? g0[j].x : (i0 == 1) ? g0[j].y
                           : (i0 == 2) ? g1[j].x : g1[j].y;
            const float s1 = (i1 == 0) ? g0[j].z : (i1 == 1) ? g0[j].w
                           : (i1 == 2) ? g1[j].z : g1[j].w;
            const size_t o = obase + (size_t)(cb + j) * (H2 * W2);
            __stcs(reinterpret_cast<float2*>(gout) + o / 2, make_float2(s0, s1));
        }
    }
}

extern "C" void kernel_launch(void* const* d_in, const int* in_sizes, int n_in,
                              void* d_out, int out_size)
{
    const float* depth = (const float*)d_in[0];
    const float* geo   = (const float*)d_in[1];
    float* out = (float*)d_out;

    const int total   = B * H2 * WP;          // 428032 threads
    const int threads = 256;
    const int blocks  = (total + threads - 1) / threads;
    sds_kernel<<<blocks, threads>>>(depth, geo, out);
}